// round 11
// baseline (speedup 1.0000x reference)
#include <cuda_runtime.h>
#include <cuda_fp16.h>
#include <cstdint>

// ---------------- Problem dims ----------------
#define B_DIM   64
#define T_DIM   500
#define IN_DIM  512
#define HID_DIM 2048
#define OUT_DIM 128
#define M_DIM   (B_DIM * T_DIM)          // 32000

// LIF constants
#define A_S1 0.81873075307798182f
#define SC1  0.90634623461009088f
#define A_M1 0.90483741803595952f
#define BM1  0.09516258196404048f
#define TH1  0.5f
#define A_S2 0.90483741803595952f
#define SC2  0.95162581964040482f
#define A_M2 0.95122942450071402f
#define BM2  0.04877057549928598f
#define TH2  1.0f

#define W1_SCALE 256.0f
#define W1_INV   0.00390625f
#define EPS_RISK 1e-4f
#define RISK_CAP 65536

// ---------------- Scratch (device globals) ----------------
__device__ float    g_c1[(size_t)M_DIM * HID_DIM];   // 262 MB
__device__ float    g_c2[(size_t)M_DIM * OUT_DIM];   // 16.4 MB
__device__ uint32_t g_bm[(size_t)M_DIM * 64];        // 8.2 MB spike bitmask
__device__ __half   g_xh [(size_t)M_DIM * 1024];     // 65.5 MB [x_hi|x_lo]
__device__ __half   g_w1h[(size_t)HID_DIM * 1024];   // 4.2 MB row n: [256*w1 hi|lo]
__device__ float    g_w1t[(size_t)HID_DIM * IN_DIM]; // 4 MB w1 transposed [h][k]
__device__ uint32_t g_risky[RISK_CAP];
__device__ uint32_t g_cnt[1];

// ---------------- PTX helpers ----------------
__device__ __forceinline__ uint32_t smem_u32(const void* p) {
    uint32_t a;
    asm("{ .reg .u64 t; cvta.to.shared.u64 t, %1; cvt.u32.u64 %0, t; }" : "=r"(a) : "l"(p));
    return a;
}
__device__ __forceinline__ void cp16(uint32_t d, const void* g) {
    asm volatile("cp.async.cg.shared.global [%0], [%1], 16;" :: "r"(d), "l"(g));
}
#define CP_COMMIT() asm volatile("cp.async.commit_group;" ::: "memory")
#define CP_WAIT1()  asm volatile("cp.async.wait_group 1;" ::: "memory")

__device__ __forceinline__ void ldsm4(uint32_t* r, uint32_t a) {
    asm volatile("ldmatrix.sync.aligned.m8n8.x4.shared.b16 {%0,%1,%2,%3}, [%4];"
        : "=r"(r[0]), "=r"(r[1]), "=r"(r[2]), "=r"(r[3]) : "r"(a));
}
__device__ __forceinline__ void mma16816(float* d, const uint32_t* a, const uint32_t* b) {
    asm volatile(
        "mma.sync.aligned.m16n8k16.row.col.f32.f16.f16.f32 "
        "{%0,%1,%2,%3}, {%4,%5,%6,%7}, {%8,%9}, {%0,%1,%2,%3};"
        : "+f"(d[0]), "+f"(d[1]), "+f"(d[2]), "+f"(d[3])
        : "r"(a[0]), "r"(a[1]), "r"(a[2]), "r"(a[3]), "r"(b[0]), "r"(b[1]));
}
#define SWZ64(o) ((o) ^ (((o) >> 3) & 0x30))

// ---------------- fp16 mma GEMM1: 3-product split, K'=1536 ----------------
// seg 0: (x_hi, w_hi)  seg 1: (x_lo, w_hi)  seg 2: (x_hi, w_lo)
// BM=256, BN=128, 512 thr / 16 warps (4x4), warp tile 64x32, 3-stage cp.async.
#define G1_NC 48
__global__ __launch_bounds__(512, 1)
void gemm1_mma(const __half* __restrict__ A, const __half* __restrict__ Bm,
               float* __restrict__ C)
{
    constexpr int BM = 256, BN = 128, WM = 64, WN = 32;
    constexpr int ABY = BM * 64, BBY = BN * 64, STG = ABY + BBY;
    constexpr int NWN = BN / WN, MT = WM / 16, NT = WN / 8;

    extern __shared__ char smem_raw[];
    uint32_t sb = (smem_u32(smem_raw) + 1023u) & ~1023u;

    const int tid  = threadIdx.x;
    const int wid  = tid >> 5;
    const int lane = tid & 31;
    const int wm   = wid / NWN;
    const int wn   = wid % NWN;
    const int m0   = blockIdx.y * BM;
    const int n0   = blockIdx.x * BN;

    float acc[MT][NT][4] = {};

    auto issue = [&](int c) {
        int seg = c >> 4, kk = c & 15;
        int acol = kk * 32 + (seg == 1 ? 512 : 0);
        int bcol = kk * 32 + (seg == 2 ? 512 : 0);
        uint32_t st = sb + (c % 3) * STG;
        #pragma unroll
        for (int i = 0; i < BM / 128; i++) {
            int s = tid + i * 512, r = s >> 2, cq = (s & 3) * 8;
            cp16(st + SWZ64(r * 64 + cq * 2),
                 A + (size_t)(m0 + r) * 1024 + acol + cq);
        }
        #pragma unroll
        for (int i = 0; i < BN / 128; i++) {
            int s = tid + i * 512, r = s >> 2, cq = (s & 3) * 8;
            cp16(st + ABY + SWZ64(r * 64 + cq * 2),
                 Bm + (size_t)(n0 + r) * 1024 + bcol + cq);
        }
        CP_COMMIT();
    };

    issue(0); issue(1);

    for (int c = 0; c < G1_NC; c++) {
        CP_WAIT1();
        __syncthreads();
        uint32_t stA = sb + (c % 3) * STG;
        uint32_t stB = stA + ABY;

        #pragma unroll
        for (int ks = 0; ks < 2; ks++) {
            uint32_t afr[MT][4], bfr[NT][2];
            int sub = lane >> 3;
            int kh  = ks * 16 + (sub >> 1) * 8;
            #pragma unroll
            for (int mt = 0; mt < MT; mt++) {
                int r = wm * WM + mt * 16 + (sub & 1) * 8 + (lane & 7);
                ldsm4(afr[mt], stA + SWZ64(r * 64 + kh * 2));
            }
            #pragma unroll
            for (int p = 0; p < NT / 2; p++) {
                int r = wn * WN + p * 16 + (sub & 1) * 8 + (lane & 7);
                uint32_t t4[4];
                ldsm4(t4, stB + SWZ64(r * 64 + kh * 2));
                bfr[2*p][0] = t4[0]; bfr[2*p][1] = t4[2];
                bfr[2*p+1][0] = t4[1]; bfr[2*p+1][1] = t4[3];
            }
            #pragma unroll
            for (int mt = 0; mt < MT; mt++)
                #pragma unroll
                for (int nt = 0; nt < NT; nt++)
                    mma16816(acc[mt][nt], afr[mt], bfr[nt]);
        }
        __syncthreads();
        if (c + 2 < G1_NC) issue(c + 2);
    }

    #pragma unroll
    for (int mt = 0; mt < MT; mt++) {
        int row = m0 + wm * WM + mt * 16 + (lane >> 2);
        #pragma unroll
        for (int nt = 0; nt < NT; nt++) {
            int col = n0 + wn * WN + nt * 8 + (lane & 3) * 2;
            float2 v0 = make_float2(acc[mt][nt][0] * W1_INV, acc[mt][nt][1] * W1_INV);
            float2 v1 = make_float2(acc[mt][nt][2] * W1_INV, acc[mt][nt][3] * W1_INV);
            *reinterpret_cast<float2*>(&C[(size_t)row * HID_DIM + col])       = v0;
            *reinterpret_cast<float2*>(&C[(size_t)(row + 8) * HID_DIM + col]) = v1;
        }
    }
}

// ---------------- prep kernels ----------------
__global__ __launch_bounds__(256)
void prep_x(const float* __restrict__ x, __half* __restrict__ xh) {
    int idx = blockIdx.x * blockDim.x + threadIdx.x;
    if (idx >= M_DIM * 128) return;
    int m = idx >> 7, q = (idx & 127) * 4;
    float4 v = *reinterpret_cast<const float4*>(x + (size_t)m * 512 + q);
    __half h[4], l[4];
    h[0] = __float2half_rn(v.x); l[0] = __float2half_rn(v.x - __half2float(h[0]));
    h[1] = __float2half_rn(v.y); l[1] = __float2half_rn(v.y - __half2float(h[1]));
    h[2] = __float2half_rn(v.z); l[2] = __float2half_rn(v.z - __half2float(h[2]));
    h[3] = __float2half_rn(v.w); l[3] = __float2half_rn(v.w - __half2float(h[3]));
    __half2* hi = reinterpret_cast<__half2*>(xh + (size_t)m * 1024 + q);
    __half2* lo = reinterpret_cast<__half2*>(xh + (size_t)m * 1024 + 512 + q);
    hi[0] = __halves2half2(h[0], h[1]); hi[1] = __halves2half2(h[2], h[3]);
    lo[0] = __halves2half2(l[0], l[1]); lo[1] = __halves2half2(l[2], l[3]);
}
__global__ __launch_bounds__(256)
void prep_w1(const float* __restrict__ w1, __half* __restrict__ w1h,
             float* __restrict__ w1t, uint32_t* __restrict__ cnt) {
    int idx = blockIdx.x * blockDim.x + threadIdx.x;
    if (idx == 0) *cnt = 0;                       // reset risky counter
    if (idx >= IN_DIM * HID_DIM) return;
    int k = idx >> 11, n = idx & 2047;
    float v = w1[idx];
    w1t[(size_t)n * IN_DIM + k] = v;              // transpose for rescue dots
    float vs = v * W1_SCALE;
    __half h = __float2half_rn(vs);
    w1h[(size_t)n * 1024 + k]       = h;
    w1h[(size_t)n * 1024 + 512 + k] = __float2half_rn(vs - __half2float(h));
}

// ---------------- Layer-1 scan: fast values + bitmask + risky detection ----------
__global__ __launch_bounds__(256)
void scan1_detect(const float* __restrict__ c1, float* __restrict__ spk1,
                  float* __restrict__ mems1, uint32_t* __restrict__ bm,
                  uint32_t* __restrict__ risky, uint32_t* __restrict__ cnt) {
    int idx = blockIdx.x * blockDim.x + threadIdx.x;
    if (idx >= B_DIM * HID_DIM) return;
    int b = idx >> 11;
    int h = idx & (HID_DIM - 1);
    int lane = threadIdx.x & 31;
    int hw = h >> 5;
    size_t base = (size_t)b * T_DIM * HID_DIM + h;
    float syn = 0.f, mem = 0.f;
    bool risk = false;
    for (int t = 0; t < T_DIM; t++) {
        size_t o = base + (size_t)t * HID_DIM;
        syn = A_S1 * syn + SC1 * c1[o];
        mem = A_M1 * mem + BM1 * syn;
        risk = risk || (fabsf(mem - TH1) < EPS_RISK);   // pre-reset decision margin
        float s = (mem - TH1 > 0.f) ? 1.f : 0.f;
        mem -= s * TH1;
        spk1[o]  = s;
        mems1[o] = mem;
        uint32_t w = __ballot_sync(0xffffffffu, s > 0.f);
        if (lane == 0) bm[((size_t)b * T_DIM + t) * 64 + hw] = w;
    }
    if (risk) {
        uint32_t p = atomicAdd(cnt, 1u);
        if (p < RISK_CAP) risky[p] = (uint32_t)idx;
    }
}

// ---------------- Rescue A: exact sequential-fp32 c1 rows for risky elements -----
__global__ __launch_bounds__(128)
void rescue_a(const float* __restrict__ x, const float* __restrict__ w1t,
              float* __restrict__ c1,
              const uint32_t* __restrict__ risky, const uint32_t* __restrict__ cnt) {
    uint32_t n = *cnt; if (n > RISK_CAP) n = RISK_CAP;
    for (uint32_t e = blockIdx.x; e < n; e += gridDim.x) {
        uint32_t idx = risky[e];
        int b = idx >> 11, h = idx & 2047;
        const float* wr = w1t + (size_t)h * IN_DIM;
        for (int t = threadIdx.x; t < T_DIM; t += 128) {
            const float* xr = x + ((size_t)b * T_DIM + t) * IN_DIM;
            float acc = 0.f;
            for (int k = 0; k < IN_DIM; k++)          // sequential ascending k:
                acc = fmaf(xr[k], wr[k], acc);        // bit-identical to R1 SGEMM
            c1[((size_t)b * T_DIM + t) * HID_DIM + h] = acc;
        }
    }
}

// ---------------- Rescue B: replay scan on risky elements, patch outputs ---------
__global__ __launch_bounds__(256)
void rescue_b(const float* __restrict__ c1, float* __restrict__ spk1,
              float* __restrict__ mems1, uint32_t* __restrict__ bm,
              const uint32_t* __restrict__ risky, const uint32_t* __restrict__ cnt) {
    uint32_t n = *cnt; if (n > RISK_CAP) n = RISK_CAP;
    uint32_t gt = blockIdx.x * blockDim.x + threadIdx.x;
    for (uint32_t e = gt; e < n; e += gridDim.x * blockDim.x) {
        uint32_t idx = risky[e];
        int b = idx >> 11, h = idx & 2047;
        int hw = h >> 5;
        uint32_t bit = 1u << (h & 31);
        size_t base = (size_t)b * T_DIM * HID_DIM + h;
        float syn = 0.f, mem = 0.f;
        for (int t = 0; t < T_DIM; t++) {
            size_t o = base + (size_t)t * HID_DIM;
            syn = A_S1 * syn + SC1 * c1[o];
            mem = A_M1 * mem + BM1 * syn;
            float s = (mem - TH1 > 0.f) ? 1.f : 0.f;
            mem -= s * TH1;
            spk1[o]  = s;
            mems1[o] = mem;
            uint32_t* wp = &bm[((size_t)b * T_DIM + t) * 64 + hw];
            if (s > 0.f) atomicOr(wp, bit);
            else         atomicAnd(wp, ~bit);
        }
    }
}

// ---------------- Sparse-exact GEMM2 (bit-identical; from R10) ----------------
#define SGK 64
__global__ __launch_bounds__(256, 2)
void spmm2_kernel(const uint32_t* __restrict__ bm, const float* __restrict__ w2,
                  float* __restrict__ c2) {
    __shared__ float ws[SGK][OUT_DIM];

    const int tid  = threadIdx.x;
    const int wid  = tid >> 5;
    const int lane = tid & 31;
    const int rbase = blockIdx.x * 128 + wid * 16;

    float acc[16][4] = {};

    for (int kt = 0; kt < HID_DIM / SGK; kt++) {
        __syncthreads();
        #pragma unroll
        for (int i = 0; i < 8; i++) {
            int s  = tid + i * 256;
            int kk = s >> 5;
            int c4 = (s & 31) * 4;
            *reinterpret_cast<float4*>(&ws[kk][c4]) =
                *reinterpret_cast<const float4*>(
                    &w2[(size_t)(kt * SGK + kk) * OUT_DIM + c4]);
        }
        __syncthreads();

        #pragma unroll
        for (int r = 0; r < 16; r++) {
            size_t m = (size_t)(rbase + r);
            uint32_t w0 = bm[m * 64 + kt * 2];
            uint32_t w1 = bm[m * 64 + kt * 2 + 1];
            while (w0) {
                int k = __ffs(w0) - 1; w0 &= w0 - 1;
                acc[r][0] += ws[k][lane];
                acc[r][1] += ws[k][lane + 32];
                acc[r][2] += ws[k][lane + 64];
                acc[r][3] += ws[k][lane + 96];
            }
            while (w1) {
                int k = __ffs(w1) - 1; w1 &= w1 - 1;
                acc[r][0] += ws[32 + k][lane];
                acc[r][1] += ws[32 + k][lane + 32];
                acc[r][2] += ws[32 + k][lane + 64];
                acc[r][3] += ws[32 + k][lane + 96];
            }
        }
    }

    #pragma unroll
    for (int r = 0; r < 16; r++) {
        float* cp = &c2[(size_t)(rbase + r) * OUT_DIM];
        cp[lane]      = acc[r][0];
        cp[lane + 32] = acc[r][1];
        cp[lane + 64] = acc[r][2];
        cp[lane + 96] = acc[r][3];
    }
}

// ---------------- Layer-2 scan + reduction (from R10) ----------------
__global__ __launch_bounds__(256)
void scan2_kernel(const float* __restrict__ c2, float* __restrict__ out,
                  float* __restrict__ spk2, float* __restrict__ mems2) {
    int idx = blockIdx.x * blockDim.x + threadIdx.x;
    if (idx >= B_DIM * OUT_DIM) return;
    int b = idx >> 7;
    int o = idx & (OUT_DIM - 1);
    size_t base = (size_t)b * T_DIM * OUT_DIM + o;
    float syn = 0.f, mem = 0.f, acc = 0.f;
    for (int t = 0; t < T_DIM; t++) {
        size_t off = base + (size_t)t * OUT_DIM;
        syn = A_S2 * syn + SC2 * c2[off];
        mem = A_M2 * mem + BM2 * syn;
        float s = (mem - TH2 > 0.f) ? 1.f : 0.f;
        mem -= s * TH2;
        spk2[off]  = s;
        mems2[off] = mem;
        if (t > 0) acc += mem;
    }
    out[(size_t)b * OUT_DIM + o] = acc / (float)T_DIM;
}

// ---------------- Launch ----------------
extern "C" void kernel_launch(void* const* d_in, const int* in_sizes, int n_in,
                              void* d_out, int out_size) {
    const float* x  = (const float*)d_in[0];
    const float* w1 = (const float*)d_in[1];
    const float* w2 = (const float*)d_in[2];

    float* out   = (float*)d_out;
    float* spk1  = out  + (size_t)B_DIM * OUT_DIM;
    float* mems1 = spk1 + (size_t)B_DIM * T_DIM * HID_DIM;
    float* spk2  = mems1 + (size_t)B_DIM * T_DIM * HID_DIM;
    float* mems2 = spk2 + (size_t)B_DIM * T_DIM * OUT_DIM;

    float*    c1;  cudaGetSymbolAddress((void**)&c1,  g_c1);
    float*    c2;  cudaGetSymbolAddress((void**)&c2,  g_c2);
    uint32_t* bm;  cudaGetSymbolAddress((void**)&bm,  g_bm);
    __half*   xh;  cudaGetSymbolAddress((void**)&xh,  g_xh);
    __half*   w1h; cudaGetSymbolAddress((void**)&w1h, g_w1h);
    float*    w1t; cudaGetSymbolAddress((void**)&w1t, g_w1t);
    uint32_t* rsk; cudaGetSymbolAddress((void**)&rsk, g_risky);
    uint32_t* cnt; cudaGetSymbolAddress((void**)&cnt, g_cnt);

    constexpr int SM1 = (256 + 128) * 64 * 3 + 1024;   // ~73 KB
    cudaFuncSetAttribute(gemm1_mma, cudaFuncAttributeMaxDynamicSharedMemorySize, SM1);

    // Prep (also resets risky counter)
    prep_x <<<(M_DIM * 128 + 255) / 256, 256>>>(x, xh);
    prep_w1<<<(IN_DIM * HID_DIM + 255) / 256, 256>>>(w1, w1h, w1t, cnt);

    // GEMM1 fast: C1 ~= X @ W1 (fp16 3-product, tensor pipe)
    {
        dim3 grid(HID_DIM / 128, M_DIM / 256);   // (16, 125)
        gemm1_mma<<<grid, 512, SM1>>>(xh, w1h, c1);
    }
    // Scan1 + risky detection
    scan1_detect<<<(B_DIM * HID_DIM) / 256, 256>>>(c1, spk1, mems1, bm, rsk, cnt);
    // Rescue: exact recompute of risky elements (bit-identical to fp32 baseline)
    rescue_a<<<8192, 128>>>(x, w1t, c1, rsk, cnt);
    rescue_b<<<256, 256>>>(c1, spk1, mems1, bm, rsk, cnt);
    // Sparse-exact GEMM2
    spmm2_kernel<<<M_DIM / 128, 256>>>(bm, w2, c2);
    // Scan2 + output
    scan2_kernel<<<(B_DIM * OUT_DIM) / 256, 256>>>(c2, out, spk2, mems2);
}

// round 12
// speedup vs baseline: 3.3524x; 3.3524x over previous
#include <cuda_runtime.h>
#include <cstdint>

// ---------------- Problem dims ----------------
#define B_DIM   64
#define T_DIM   500
#define IN_DIM  512
#define HID_DIM 2048
#define OUT_DIM 128
#define M_DIM   (B_DIM * T_DIM)          // 32000

// LIF constants
#define A_S1 0.81873075307798182f
#define SC1  0.90634623461009088f
#define A_M1 0.90483741803595952f
#define BM1  0.09516258196404048f
#define TH1  0.5f
#define A_S2 0.90483741803595952f
#define SC2  0.95162581964040482f
#define A_M2 0.95122942450071402f
#define BM2  0.04877057549928598f
#define TH2  1.0f

typedef unsigned long long ull;

// ---------------- Scratch (device globals) ----------------
__device__ float    g_c1[(size_t)M_DIM * HID_DIM];   // 262 MB: X @ W1
__device__ float    g_c2[(size_t)M_DIM * OUT_DIM];   // 16.4 MB: spk1 @ W2
__device__ uint32_t g_bm[(size_t)M_DIM * 64];        // 8.2 MB spike bitmask

// ---------------- packed f32x2 helpers ----------------
__device__ __forceinline__ ull pk2(float v) {
    ull r;
    asm("mov.b64 %0, {%1, %1};" : "=l"(r) : "r"(__float_as_uint(v)));
    return r;
}
__device__ __forceinline__ void fma2(ull& d, ull a, ull b) {
    asm("fma.rn.f32x2 %0, %1, %2, %0;" : "+l"(d) : "l"(a), "l"(b));
}
__device__ __forceinline__ void add2(ull& d, ull a) {
    asm("add.rn.f32x2 %0, %0, %1;" : "+l"(d) : "l"(a));
}

// ---------------- SGEMM1 with packed f32x2 (bit-identical k-order to R1) ---------
// C[M x N] = A[M x K] @ B[K x N]. BM=BN=128, BK=16, 256 thr, 8x8 microtile.
// A smem tile stored pre-duplicated ({v,v} 64-bit) -> one LDS.64 broadcast per
// fragment; B pairs read as native 64-bit words. 32 FFMA2/k/thread vs 64 FFMA.
// Per element: one IEEE fp32 FMA per k, k strictly ascending -> bit-exact vs R1.
#define GBM 128
#define GBN 128
#define GBK 16

__global__ __launch_bounds__(256, 2)
void sgemm1_x2(const float* __restrict__ A, const float* __restrict__ B,
               float* __restrict__ C, int M, int N, int K) {
    __shared__ ull   As2[GBK][GBM];   // 16 KB, duplicated pairs
    __shared__ float Bs[GBK][GBN];    //  8 KB

    const int tid  = threadIdx.x;
    const int brow = blockIdx.y * GBM;
    const int bcol = blockIdx.x * GBN;

    const int trow = (tid >> 4) << 3;     // 0..120 step 8
    const int tcol = (tid & 15) << 3;     // 0..120 step 8

    ull acc2[8][4];
    #pragma unroll
    for (int u = 0; u < 8; u++)
        #pragma unroll
        for (int j = 0; j < 4; j++) acc2[u][j] = 0ull;   // {0.f,0.f}

    for (int k0 = 0; k0 < K; k0 += GBK) {
        #pragma unroll
        for (int i = 0; i < 2; i++) {
            int s   = tid + i * 256;
            int row = s >> 2;
            int kc  = (s & 3) << 2;
            float4 v = *reinterpret_cast<const float4*>(
                &A[(size_t)(brow + row) * K + k0 + kc]);
            As2[kc + 0][row] = pk2(v.x);
            As2[kc + 1][row] = pk2(v.y);
            As2[kc + 2][row] = pk2(v.z);
            As2[kc + 3][row] = pk2(v.w);
        }
        #pragma unroll
        for (int i = 0; i < 2; i++) {
            int s   = tid + i * 256;
            int row = s >> 5;
            int c4  = (s & 31) << 2;
            *reinterpret_cast<float4*>(&Bs[row][c4]) =
                *reinterpret_cast<const float4*>(
                    &B[(size_t)(k0 + row) * N + bcol + c4]);
        }
        __syncthreads();

        #pragma unroll
        for (int k = 0; k < GBK; k++) {
            ull ar2[8], br2[4];
            #pragma unroll
            for (int u = 0; u < 8; u++) ar2[u] = As2[k][trow + u];  // LDS.64 bcast
            const ull* bp = reinterpret_cast<const ull*>(&Bs[k][tcol]);
            #pragma unroll
            for (int j = 0; j < 4; j++) br2[j] = bp[j];             // column pairs
            #pragma unroll
            for (int u = 0; u < 8; u++)
                #pragma unroll
                for (int j = 0; j < 4; j++)
                    fma2(acc2[u][j], ar2[u], br2[j]);
        }
        __syncthreads();
    }

    #pragma unroll
    for (int u = 0; u < 8; u++) {
        ull* cp = reinterpret_cast<ull*>(&C[(size_t)(brow + trow + u) * N + bcol + tcol]);
        ulonglong2 v0; v0.x = acc2[u][0]; v0.y = acc2[u][1];
        ulonglong2 v1; v1.x = acc2[u][2]; v1.y = acc2[u][3];
        *reinterpret_cast<ulonglong2*>(cp)     = v0;
        *reinterpret_cast<ulonglong2*>(cp + 2) = v1;
    }
}

// ---------------- Layer-1 LIF scan (+ spike bitmask via ballot) ----------------
__global__ __launch_bounds__(256)
void scan1_kernel(const float* __restrict__ c1, float* __restrict__ spk1,
                  float* __restrict__ mems1, uint32_t* __restrict__ bm) {
    int idx = blockIdx.x * blockDim.x + threadIdx.x;
    if (idx >= B_DIM * HID_DIM) return;
    int b = idx >> 11;
    int h = idx & (HID_DIM - 1);
    int lane = threadIdx.x & 31;
    int hw = h >> 5;
    size_t base = (size_t)b * T_DIM * HID_DIM + h;
    float syn = 0.f, mem = 0.f;
    for (int t = 0; t < T_DIM; t++) {
        size_t o = base + (size_t)t * HID_DIM;
        syn = A_S1 * syn + SC1 * c1[o];
        mem = A_M1 * mem + BM1 * syn;
        float s = (mem - TH1 > 0.f) ? 1.f : 0.f;
        mem -= s * TH1;
        spk1[o]  = s;
        mems1[o] = mem;
        uint32_t w = __ballot_sync(0xffffffffu, s > 0.f);
        if (lane == 0) bm[((size_t)b * T_DIM + t) * 64 + hw] = w;
    }
}

// ---------------- Sparse-exact GEMM2 with f32x2 adds ----------------
// Bit-identical to dense ascending-k fp32 chain: skip s=0, acc=RN(acc+w) for s=1.
// Lane covers column pairs {2*lane, 2*lane+1} and {64+2*lane, 64+2*lane+1}.
#define SGK 64
__global__ __launch_bounds__(256, 2)
void spmm2_kernel(const uint32_t* __restrict__ bm, const float* __restrict__ w2,
                  float* __restrict__ c2) {
    __shared__ float ws[SGK][OUT_DIM];

    const int tid  = threadIdx.x;
    const int wid  = tid >> 5;
    const int lane = tid & 31;
    const int rbase = blockIdx.x * 128 + wid * 16;

    ull acc2[16][2];
    #pragma unroll
    for (int r = 0; r < 16; r++) { acc2[r][0] = 0ull; acc2[r][1] = 0ull; }

    for (int kt = 0; kt < HID_DIM / SGK; kt++) {
        __syncthreads();
        #pragma unroll
        for (int i = 0; i < 8; i++) {
            int s  = tid + i * 256;
            int kk = s >> 5;
            int c4 = (s & 31) * 4;
            *reinterpret_cast<float4*>(&ws[kk][c4]) =
                *reinterpret_cast<const float4*>(
                    &w2[(size_t)(kt * SGK + kk) * OUT_DIM + c4]);
        }
        __syncthreads();

        #pragma unroll
        for (int r = 0; r < 16; r++) {
            size_t m = (size_t)(rbase + r);
            uint32_t w0 = bm[m * 64 + kt * 2];
            uint32_t w1 = bm[m * 64 + kt * 2 + 1];
            while (w0) {
                int k = __ffs(w0) - 1; w0 &= w0 - 1;
                const ull* wp = reinterpret_cast<const ull*>(&ws[k][0]);
                add2(acc2[r][0], wp[lane]);
                add2(acc2[r][1], wp[32 + lane]);
            }
            while (w1) {
                int k = __ffs(w1) - 1; w1 &= w1 - 1;
                const ull* wp = reinterpret_cast<const ull*>(&ws[32 + k][0]);
                add2(acc2[r][0], wp[lane]);
                add2(acc2[r][1], wp[32 + lane]);
            }
        }
    }

    #pragma unroll
    for (int r = 0; r < 16; r++) {
        float* cp = &c2[(size_t)(rbase + r) * OUT_DIM];
        *reinterpret_cast<ull*>(&cp[2 * lane])      = acc2[r][0];
        *reinterpret_cast<ull*>(&cp[64 + 2 * lane]) = acc2[r][1];
    }
}

// ---------------- Layer-2 LIF scan + time reduction ----------------
__global__ __launch_bounds__(256)
void scan2_kernel(const float* __restrict__ c2, float* __restrict__ out,
                  float* __restrict__ spk2, float* __restrict__ mems2) {
    int idx = blockIdx.x * blockDim.x + threadIdx.x;
    if (idx >= B_DIM * OUT_DIM) return;
    int b = idx >> 7;
    int o = idx & (OUT_DIM - 1);
    size_t base = (size_t)b * T_DIM * OUT_DIM + o;
    float syn = 0.f, mem = 0.f, acc = 0.f;
    for (int t = 0; t < T_DIM; t++) {
        size_t off = base + (size_t)t * OUT_DIM;
        syn = A_S2 * syn + SC2 * c2[off];
        mem = A_M2 * mem + BM2 * syn;
        float s = (mem - TH2 > 0.f) ? 1.f : 0.f;
        mem -= s * TH2;
        spk2[off]  = s;
        mems2[off] = mem;
        if (t > 0) acc += mem;
    }
    out[(size_t)b * OUT_DIM + o] = acc / (float)T_DIM;
}

// ---------------- Launch ----------------
extern "C" void kernel_launch(void* const* d_in, const int* in_sizes, int n_in,
                              void* d_out, int out_size) {
    const float* x  = (const float*)d_in[0];   // [B, T, IN]
    const float* w1 = (const float*)d_in[1];   // [IN, HID]
    const float* w2 = (const float*)d_in[2];   // [HID, OUT]

    float* out   = (float*)d_out;
    float* spk1  = out  + (size_t)B_DIM * OUT_DIM;
    float* mems1 = spk1 + (size_t)B_DIM * T_DIM * HID_DIM;
    float* spk2  = mems1 + (size_t)B_DIM * T_DIM * HID_DIM;
    float* mems2 = spk2 + (size_t)B_DIM * T_DIM * OUT_DIM;

    float*    c1; cudaGetSymbolAddress((void**)&c1, g_c1);
    float*    c2; cudaGetSymbolAddress((void**)&c2, g_c2);
    uint32_t* bm; cudaGetSymbolAddress((void**)&bm, g_bm);

    // Stage 1: C1 = X @ W1 (f32x2 packed FFMA, bit-exact vs R1)
    {
        dim3 grid(HID_DIM / GBN, M_DIM / GBM);   // 16 x 250
        sgemm1_x2<<<grid, 256>>>(x, w1, c1, M_DIM, HID_DIM, IN_DIM);
    }
    // Stage 2: layer-1 scan -> spk1, mems1, bitmask
    scan1_kernel<<<(B_DIM * HID_DIM) / 256, 256>>>(c1, spk1, mems1, bm);
    // Stage 3: C2 = spk1 @ W2 via sparse-exact bitmask GEMM (f32x2 adds)
    spmm2_kernel<<<M_DIM / 128, 256>>>(bm, w2, c2);
    // Stage 4: layer-2 scan + output reduction
    scan2_kernel<<<(B_DIM * OUT_DIM) / 256, 256>>>(c2, out, spk2, mems2);
}

// round 13
// speedup vs baseline: 3.6094x; 1.0767x over previous
#include <cuda_runtime.h>
#include <cstdint>

// ---------------- Problem dims ----------------
#define B_DIM   64
#define T_DIM   500
#define IN_DIM  512
#define HID_DIM 2048
#define OUT_DIM 128
#define M_DIM   (B_DIM * T_DIM)          // 32000

#define NCHUNK  4
#define HCH     (HID_DIM / NCHUNK)       // 512 h-columns per chunk

// LIF constants
#define A_S1 0.81873075307798182f
#define SC1  0.90634623461009088f
#define A_M1 0.90483741803595952f
#define BM1  0.09516258196404048f
#define TH1  0.5f
#define A_S2 0.90483741803595952f
#define SC2  0.95162581964040482f
#define A_M2 0.95122942450071402f
#define BM2  0.04877057549928598f
#define TH2  1.0f

// ---------------- Scratch (device globals) ----------------
__device__ float    g_c1[(size_t)M_DIM * HID_DIM];   // 262 MB: X @ W1
__device__ float    g_c2[(size_t)M_DIM * OUT_DIM];   // 16.4 MB: spk1 @ W2 (prefix acc)
__device__ uint32_t g_bm[(size_t)M_DIM * 64];        // 8.2 MB spike bitmask

// ---------------- SGEMM1 (R1 arithmetic, bit-exact; A-frag via LDS.64) ----------
// C[M x HID] = A[M x 512] @ B[512 x HID], h-chunked: B/C pointers pre-offset by
// chunk column base; ld stays HID_DIM. BM=BN=128, BK=16, 256 thr, 8x8 microtile.
// k strictly ascending per element -> bit-identical to R1 baseline.
#define GBM 128
#define GBN 128
#define GBK 16

__global__ __launch_bounds__(256, 2)
void sgemm1_kernel(const float* __restrict__ A, const float* __restrict__ B,
                   float* __restrict__ C) {
    __shared__ float As[GBK][GBM];   // transposed A tile
    __shared__ float Bs[GBK][GBN];

    const int tid  = threadIdx.x;
    const int brow = blockIdx.y * GBM;
    const int bcol = blockIdx.x * GBN;          // within the 512-wide chunk

    const int trow = (tid >> 4) << 3;           // 0..120 step 8
    const int tcol = (tid & 15) << 3;           // 0..120 step 8

    float acc[8][8] = {};

    for (int k0 = 0; k0 < IN_DIM; k0 += GBK) {
        #pragma unroll
        for (int i = 0; i < 2; i++) {
            int s   = tid + i * 256;
            int row = s >> 2;
            int kc  = (s & 3) << 2;
            float4 v = *reinterpret_cast<const float4*>(
                &A[(size_t)(brow + row) * IN_DIM + k0 + kc]);
            As[kc + 0][row] = v.x;
            As[kc + 1][row] = v.y;
            As[kc + 2][row] = v.z;
            As[kc + 3][row] = v.w;
        }
        #pragma unroll
        for (int i = 0; i < 2; i++) {
            int s   = tid + i * 256;
            int row = s >> 5;
            int c4  = (s & 31) << 2;
            *reinterpret_cast<float4*>(&Bs[row][c4]) =
                *reinterpret_cast<const float4*>(
                    &B[(size_t)(k0 + row) * HID_DIM + bcol + c4]);
        }
        __syncthreads();

        #pragma unroll
        for (int k = 0; k < GBK; k++) {
            float ar[8], br[8];
            // A fragment: 4x LDS.64 (broadcast within 16-thread row group)
            #pragma unroll
            for (int p = 0; p < 4; p++) {
                float2 a2 = *reinterpret_cast<const float2*>(&As[k][trow + 2 * p]);
                ar[2 * p]     = a2.x;
                ar[2 * p + 1] = a2.y;
            }
            *reinterpret_cast<float4*>(&br[0]) =
                *reinterpret_cast<const float4*>(&Bs[k][tcol]);
            *reinterpret_cast<float4*>(&br[4]) =
                *reinterpret_cast<const float4*>(&Bs[k][tcol + 4]);
            #pragma unroll
            for (int u = 0; u < 8; u++)
                #pragma unroll
                for (int v = 0; v < 8; v++)
                    acc[u][v] = fmaf(ar[u], br[v], acc[u][v]);
        }
        __syncthreads();
    }

    #pragma unroll
    for (int u = 0; u < 8; u++)
        #pragma unroll
        for (int v = 0; v < 8; v += 4) {
            float4 w = make_float4(acc[u][v], acc[u][v+1], acc[u][v+2], acc[u][v+3]);
            *reinterpret_cast<float4*>(
                &C[(size_t)(brow + trow + u) * HID_DIM + bcol + tcol + v]) = w;
        }
}

// ---------------- Layer-1 LIF scan for one h-chunk (+ ballot bitmask) ------------
__global__ __launch_bounds__(256)
void scan1_kernel(const float* __restrict__ c1, float* __restrict__ spk1,
                  float* __restrict__ mems1, uint32_t* __restrict__ bm, int hbase) {
    int idx = blockIdx.x * blockDim.x + threadIdx.x;    // 0 .. B_DIM*HCH-1
    if (idx >= B_DIM * HCH) return;
    int b  = idx / HCH;
    int h  = hbase + (idx % HCH);
    int lane = threadIdx.x & 31;
    int hw = h >> 5;
    size_t base = (size_t)b * T_DIM * HID_DIM + h;
    float syn = 0.f, mem = 0.f;
    for (int t = 0; t < T_DIM; t++) {
        size_t o = base + (size_t)t * HID_DIM;
        syn = A_S1 * syn + SC1 * c1[o];
        mem = A_M1 * mem + BM1 * syn;
        float s = (mem - TH1 > 0.f) ? 1.f : 0.f;
        mem -= s * TH1;
        spk1[o]  = s;
        mems1[o] = mem;
        uint32_t w = __ballot_sync(0xffffffffu, s > 0.f);
        if (lane == 0) bm[((size_t)b * T_DIM + t) * 64 + hw] = w;
    }
}

// ---------------- Sparse-exact GEMM2, k-chunked with exact prefix accumulation ---
// Chunk c covers k in [c*512, (c+1)*512): kt tiles [c*8, c*8+8). c2 holds the
// exact RN-prefix after each chunk; continuing adds in ascending k preserves the
// dense sequential fp32 chain bit-exactly.
#define SGK 64
__global__ __launch_bounds__(256, 2)
void spmm2_kernel(const uint32_t* __restrict__ bm, const float* __restrict__ w2,
                  float* __restrict__ c2, int chunk) {
    __shared__ float ws[SGK][OUT_DIM];

    const int tid  = threadIdx.x;
    const int wid  = tid >> 5;
    const int lane = tid & 31;
    const int rbase = blockIdx.x * 128 + wid * 16;

    float acc[16][4];
    if (chunk == 0) {
        #pragma unroll
        for (int r = 0; r < 16; r++)
            #pragma unroll
            for (int j = 0; j < 4; j++) acc[r][j] = 0.f;
    } else {
        #pragma unroll
        for (int r = 0; r < 16; r++) {
            const float* cp = &c2[(size_t)(rbase + r) * OUT_DIM];
            acc[r][0] = cp[lane];
            acc[r][1] = cp[lane + 32];
            acc[r][2] = cp[lane + 64];
            acc[r][3] = cp[lane + 96];
        }
    }

    const int kt0 = chunk * (HCH / SGK);              // 8 kt tiles per chunk
    for (int kt = kt0; kt < kt0 + HCH / SGK; kt++) {
        __syncthreads();
        #pragma unroll
        for (int i = 0; i < 8; i++) {
            int s  = tid + i * 256;
            int kk = s >> 5;
            int c4 = (s & 31) * 4;
            *reinterpret_cast<float4*>(&ws[kk][c4]) =
                *reinterpret_cast<const float4*>(
                    &w2[(size_t)(kt * SGK + kk) * OUT_DIM + c4]);
        }
        __syncthreads();

        #pragma unroll
        for (int r = 0; r < 16; r++) {
            size_t m = (size_t)(rbase + r);
            uint32_t w0 = bm[m * 64 + kt * 2];
            uint32_t w1 = bm[m * 64 + kt * 2 + 1];
            while (w0) {
                int k = __ffs(w0) - 1; w0 &= w0 - 1;
                acc[r][0] += ws[k][lane];
                acc[r][1] += ws[k][lane + 32];
                acc[r][2] += ws[k][lane + 64];
                acc[r][3] += ws[k][lane + 96];
            }
            while (w1) {
                int k = __ffs(w1) - 1; w1 &= w1 - 1;
                acc[r][0] += ws[32 + k][lane];
                acc[r][1] += ws[32 + k][lane + 32];
                acc[r][2] += ws[32 + k][lane + 64];
                acc[r][3] += ws[32 + k][lane + 96];
            }
        }
    }

    #pragma unroll
    for (int r = 0; r < 16; r++) {
        float* cp = &c2[(size_t)(rbase + r) * OUT_DIM];
        cp[lane]      = acc[r][0];
        cp[lane + 32] = acc[r][1];
        cp[lane + 64] = acc[r][2];
        cp[lane + 96] = acc[r][3];
    }
}

// ---------------- Layer-2 LIF scan + time reduction ----------------
__global__ __launch_bounds__(256)
void scan2_kernel(const float* __restrict__ c2, float* __restrict__ out,
                  float* __restrict__ spk2, float* __restrict__ mems2) {
    int idx = blockIdx.x * blockDim.x + threadIdx.x;
    if (idx >= B_DIM * OUT_DIM) return;
    int b = idx >> 7;
    int o = idx & (OUT_DIM - 1);
    size_t base = (size_t)b * T_DIM * OUT_DIM + o;
    float syn = 0.f, mem = 0.f, acc = 0.f;
    for (int t = 0; t < T_DIM; t++) {
        size_t off = base + (size_t)t * OUT_DIM;
        syn = A_S2 * syn + SC2 * c2[off];
        mem = A_M2 * mem + BM2 * syn;
        float s = (mem - TH2 > 0.f) ? 1.f : 0.f;
        mem -= s * TH2;
        spk2[off]  = s;
        mems2[off] = mem;
        if (t > 0) acc += mem;
    }
    out[(size_t)b * OUT_DIM + o] = acc / (float)T_DIM;
}

// ---------------- Launch: 2-stream chunked pipeline ----------------
extern "C" void kernel_launch(void* const* d_in, const int* in_sizes, int n_in,
                              void* d_out, int out_size) {
    const float* x  = (const float*)d_in[0];   // [B, T, IN]
    const float* w1 = (const float*)d_in[1];   // [IN, HID]
    const float* w2 = (const float*)d_in[2];   // [HID, OUT]

    float* out   = (float*)d_out;
    float* spk1  = out  + (size_t)B_DIM * OUT_DIM;
    float* mems1 = spk1 + (size_t)B_DIM * T_DIM * HID_DIM;
    float* spk2  = mems1 + (size_t)B_DIM * T_DIM * HID_DIM;
    float* mems2 = spk2 + (size_t)B_DIM * T_DIM * OUT_DIM;

    float*    c1; cudaGetSymbolAddress((void**)&c1, g_c1);
    float*    c2; cudaGetSymbolAddress((void**)&c2, g_c2);
    uint32_t* bm; cudaGetSymbolAddress((void**)&bm, g_bm);

    // Side stream + events, created once on the eager (non-capture) first call.
    static cudaStream_t s2 = []{
        cudaStream_t s; cudaStreamCreateWithFlags(&s, cudaStreamNonBlocking); return s;
    }();
    static cudaEvent_t evA[NCHUNK] = {};
    static cudaEvent_t evB = []{
        for (int i = 0; i < NCHUNK; i++)
            cudaEventCreateWithFlags(&evA[i], cudaEventDisableTiming);
        cudaEvent_t e; cudaEventCreateWithFlags(&e, cudaEventDisableTiming); return e;
    }();

    for (int c = 0; c < NCHUNK; c++) {
        // GEMM1 chunk on main (default) stream: columns [c*512, (c+1)*512)
        dim3 grid(HCH / GBN, M_DIM / GBM);           // (4, 250)
        sgemm1_kernel<<<grid, 256>>>(x, w1 + c * HCH, c1 + c * HCH);
        cudaEventRecord(evA[c], 0);

        // Dependent scan1 + spmm2 chunk on side stream (overlaps next GEMM chunk)
        cudaStreamWaitEvent(s2, evA[c], 0);
        scan1_kernel<<<(B_DIM * HCH) / 256, 256, 0, s2>>>(
            c1, spk1, mems1, bm, c * HCH);
        spmm2_kernel<<<M_DIM / 128, 256, 0, s2>>>(bm, w2, c2, c);
    }
    cudaEventRecord(evB, s2);
    cudaStreamWaitEvent(0, evB, 0);

    // Final: layer-2 scan + output reduction on main stream
    scan2_kernel<<<(B_DIM * OUT_DIM) / 256, 256>>>(c2, out, spk2, mems2);
}

// round 15
// speedup vs baseline: 4.1823x; 1.1587x over previous
#include <cuda_runtime.h>
#include <cstdint>

// ---------------- Problem dims ----------------
#define B_DIM   64
#define T_DIM   500
#define IN_DIM  512
#define HID_DIM 2048
#define OUT_DIM 128
#define M_DIM   (B_DIM * T_DIM)          // 32000

// LIF constants
#define A_S1 0.81873075307798182f
#define SC1  0.90634623461009088f
#define A_M1 0.90483741803595952f
#define BM1  0.09516258196404048f
#define TH1  0.5f
#define A_S2 0.90483741803595952f
#define SC2  0.95162581964040482f
#define A_M2 0.95122942450071402f
#define BM2  0.04877057549928598f
#define TH2  1.0f

// ---------------- Scratch (device globals) ----------------
__device__ float    g_c1[(size_t)M_DIM * HID_DIM];   // 262 MB: X @ W1
__device__ float    g_c2[(size_t)M_DIM * OUT_DIM];   // 16.4 MB: spk1 @ W2
__device__ uint32_t g_bm[(size_t)M_DIM * 64];        // 8.2 MB spike bitmask

// ---------------- SGEMM1: conflict-free fragment raster (bit-exact vs R1) --------
// C[M x N] = A[M x K] @ B[K x N]. BM=BN=128, BK=16, 256 threads.
// Thread (ty,tx) = (tid>>4, tid&15) owns rows {4ty..4ty+3, 64+4ty..+3} x
// cols {4tx..+3, 64+4tx..+3}. Per k: 2 LDS.128 A-broadcasts + 2 conflict-free
// LDS.128 B loads. Per output element k accumulates ascending -> bit-exact.
#define GBM 128
#define GBN 128
#define GBK 16
#define APAD 132                          // pad keeps 16B align, spreads STS banks

__global__ __launch_bounds__(256, 2)
void sgemm1_kernel(const float* __restrict__ A, const float* __restrict__ B,
                   float* __restrict__ C, int M, int N, int K) {
    __shared__ float As[GBK][APAD];       // transposed A tile (k-major rows)
    __shared__ float Bs[GBK][GBN];

    const int tid  = threadIdx.x;
    const int ty   = tid >> 4;            // 0..15
    const int tx   = tid & 15;            // 0..15
    const int brow = blockIdx.y * GBM;
    const int bcol = blockIdx.x * GBN;

    float acc[8][8] = {};                 // [row: 4ty+u | 64+4ty+(u-4)][col: same split]

    for (int k0 = 0; k0 < K; k0 += GBK) {
        // A tile: 128 rows x 16 k, transposed into As. 2 float4 per thread.
        #pragma unroll
        for (int i = 0; i < 2; i++) {
            int s   = tid + i * 256;
            int row = s >> 2;
            int kc  = (s & 3) << 2;
            float4 v = *reinterpret_cast<const float4*>(
                &A[(size_t)(brow + row) * K + k0 + kc]);
            As[kc + 0][row] = v.x;
            As[kc + 1][row] = v.y;
            As[kc + 2][row] = v.z;
            As[kc + 3][row] = v.w;
        }
        // B tile: 16 k x 128 cols. 2 float4 per thread.
        #pragma unroll
        for (int i = 0; i < 2; i++) {
            int s   = tid + i * 256;
            int row = s >> 5;
            int c4  = (s & 31) << 2;
            *reinterpret_cast<float4*>(&Bs[row][c4]) =
                *reinterpret_cast<const float4*>(
                    &B[(size_t)(k0 + row) * N + bcol + c4]);
        }
        __syncthreads();

        #pragma unroll
        for (int k = 0; k < GBK; k++) {
            float4 a0 = *reinterpret_cast<const float4*>(&As[k][4 * ty]);
            float4 a1 = *reinterpret_cast<const float4*>(&As[k][64 + 4 * ty]);
            float4 b0 = *reinterpret_cast<const float4*>(&Bs[k][4 * tx]);
            float4 b1 = *reinterpret_cast<const float4*>(&Bs[k][64 + 4 * tx]);
            float ar[8] = {a0.x, a0.y, a0.z, a0.w, a1.x, a1.y, a1.z, a1.w};
            float br[8] = {b0.x, b0.y, b0.z, b0.w, b1.x, b1.y, b1.z, b1.w};
            #pragma unroll
            for (int u = 0; u < 8; u++)
                #pragma unroll
                for (int v = 0; v < 8; v++)
                    acc[u][v] = fmaf(ar[u], br[v], acc[u][v]);
        }
        __syncthreads();
    }

    // Store: row halves {4ty+i, 64+4ty+i}, col halves {4tx, 64+4tx}
    #pragma unroll
    for (int i = 0; i < 4; i++) {
        float* r0 = &C[(size_t)(brow + 4 * ty + i) * N + bcol];
        float* r1 = &C[(size_t)(brow + 64 + 4 * ty + i) * N + bcol];
        *reinterpret_cast<float4*>(r0 + 4 * tx) =
            make_float4(acc[i][0], acc[i][1], acc[i][2], acc[i][3]);
        *reinterpret_cast<float4*>(r0 + 64 + 4 * tx) =
            make_float4(acc[i][4], acc[i][5], acc[i][6], acc[i][7]);
        *reinterpret_cast<float4*>(r1 + 4 * tx) =
            make_float4(acc[4 + i][0], acc[4 + i][1], acc[4 + i][2], acc[4 + i][3]);
        *reinterpret_cast<float4*>(r1 + 64 + 4 * tx) =
            make_float4(acc[4 + i][4], acc[4 + i][5], acc[4 + i][6], acc[4 + i][7]);
    }
}

// ---------------- Layer-1 LIF scan (+ spike bitmask via ballot) ----------------
__global__ __launch_bounds__(256)
void scan1_kernel(const float* __restrict__ c1, float* __restrict__ spk1,
                  float* __restrict__ mems1, uint32_t* __restrict__ bm) {
    int idx = blockIdx.x * blockDim.x + threadIdx.x;
    if (idx >= B_DIM * HID_DIM) return;
    int b = idx >> 11;
    int h = idx & (HID_DIM - 1);
    int lane = threadIdx.x & 31;
    int hw = h >> 5;
    size_t base = (size_t)b * T_DIM * HID_DIM + h;
    float syn = 0.f, mem = 0.f;
    for (int t = 0; t < T_DIM; t++) {
        size_t o = base + (size_t)t * HID_DIM;
        syn = A_S1 * syn + SC1 * c1[o];
        mem = A_M1 * mem + BM1 * syn;
        float s = (mem - TH1 > 0.f) ? 1.f : 0.f;
        mem -= s * TH1;
        spk1[o]  = s;
        mems1[o] = mem;
        uint32_t w = __ballot_sync(0xffffffffu, s > 0.f);
        if (lane == 0) bm[((size_t)b * T_DIM + t) * 64 + hw] = w;
    }
}

// ---------------- Sparse-exact GEMM2 (bit-identical; from R10) ----------------
#define SGK 64
__global__ __launch_bounds__(256, 2)
void spmm2_kernel(const uint32_t* __restrict__ bm, const float* __restrict__ w2,
                  float* __restrict__ c2) {
    __shared__ float ws[SGK][OUT_DIM];

    const int tid  = threadIdx.x;
    const int wid  = tid >> 5;
    const int lane = tid & 31;
    const int rbase = blockIdx.x * 128 + wid * 16;

    float acc[16][4] = {};

    for (int kt = 0; kt < HID_DIM / SGK; kt++) {
        __syncthreads();
        #pragma unroll
        for (int i = 0; i < 8; i++) {
            int s  = tid + i * 256;
            int kk = s >> 5;
            int c4 = (s & 31) * 4;
            *reinterpret_cast<float4*>(&ws[kk][c4]) =
                *reinterpret_cast<const float4*>(
                    &w2[(size_t)(kt * SGK + kk) * OUT_DIM + c4]);
        }
        __syncthreads();

        #pragma unroll
        for (int r = 0; r < 16; r++) {
            size_t m = (size_t)(rbase + r);
            uint32_t w0 = bm[m * 64 + kt * 2];
            uint32_t w1 = bm[m * 64 + kt * 2 + 1];
            while (w0) {
                int k = __ffs(w0) - 1; w0 &= w0 - 1;
                acc[r][0] += ws[k][lane];
                acc[r][1] += ws[k][lane + 32];
                acc[r][2] += ws[k][lane + 64];
                acc[r][3] += ws[k][lane + 96];
            }
            while (w1) {
                int k = __ffs(w1) - 1; w1 &= w1 - 1;
                acc[r][0] += ws[32 + k][lane];
                acc[r][1] += ws[32 + k][lane + 32];
                acc[r][2] += ws[32 + k][lane + 64];
                acc[r][3] += ws[32 + k][lane + 96];
            }
        }
    }

    #pragma unroll
    for (int r = 0; r < 16; r++) {
        float* cp = &c2[(size_t)(rbase + r) * OUT_DIM];
        cp[lane]      = acc[r][0];
        cp[lane + 32] = acc[r][1];
        cp[lane + 64] = acc[r][2];
        cp[lane + 96] = acc[r][3];
    }
}

// ---------------- Layer-2 LIF scan + time reduction ----------------
__global__ __launch_bounds__(256)
void scan2_kernel(const float* __restrict__ c2, float* __restrict__ out,
                  float* __restrict__ spk2, float* __restrict__ mems2) {
    int idx = blockIdx.x * blockDim.x + threadIdx.x;
    if (idx >= B_DIM * OUT_DIM) return;
    int b = idx >> 7;
    int o = idx & (OUT_DIM - 1);
    size_t base = (size_t)b * T_DIM * OUT_DIM + o;
    float syn = 0.f, mem = 0.f, acc = 0.f;
    for (int t = 0; t < T_DIM; t++) {
        size_t off = base + (size_t)t * OUT_DIM;
        syn = A_S2 * syn + SC2 * c2[off];
        mem = A_M2 * mem + BM2 * syn;
        float s = (mem - TH2 > 0.f) ? 1.f : 0.f;
        mem -= s * TH2;
        spk2[off]  = s;
        mems2[off] = mem;
        if (t > 0) acc += mem;
    }
    out[(size_t)b * OUT_DIM + o] = acc / (float)T_DIM;
}

// ---------------- Launch ----------------
extern "C" void kernel_launch(void* const* d_in, const int* in_sizes, int n_in,
                              void* d_out, int out_size) {
    const float* x  = (const float*)d_in[0];   // [B, T, IN]
    const float* w1 = (const float*)d_in[1];   // [IN, HID]
    const float* w2 = (const float*)d_in[2];   // [HID, OUT]

    float* out   = (float*)d_out;
    float* spk1  = out  + (size_t)B_DIM * OUT_DIM;
    float* mems1 = spk1 + (size_t)B_DIM * T_DIM * HID_DIM;
    float* spk2  = mems1 + (size_t)B_DIM * T_DIM * HID_DIM;
    float* mems2 = spk2 + (size_t)B_DIM * T_DIM * OUT_DIM;

    float*    c1; cudaGetSymbolAddress((void**)&c1, g_c1);
    float*    c2; cudaGetSymbolAddress((void**)&c2, g_c2);
    uint32_t* bm; cudaGetSymbolAddress((void**)&bm, g_bm);

    // Stage 1: C1 = X @ W1 (conflict-free raster SGEMM, bit-exact)
    {
        dim3 grid(HID_DIM / GBN, M_DIM / GBM);   // 16 x 250
        sgemm1_kernel<<<grid, 256>>>(x, w1, c1, M_DIM, HID_DIM, IN_DIM);
    }
    // Stage 2: layer-1 scan -> spk1, mems1, bitmask
    scan1_kernel<<<(B_DIM * HID_DIM) / 256, 256>>>(c1, spk1, mems1, bm);
    // Stage 3: C2 = spk1 @ W2 via sparse-exact bitmask GEMM
    spmm2_kernel<<<M_DIM / 128, 256>>>(bm, w2, c2);
    // Stage 4: layer-2 scan + output reduction
    scan2_kernel<<<(B_DIM * OUT_DIM) / 256, 256>>>(c2, out, spk2, mems2);
}

// round 16
// speedup vs baseline: 4.5925x; 1.0981x over previous
#include <cuda_runtime.h>
#include <cstdint>

// ---------------- Problem dims ----------------
#define B_DIM   64
#define T_DIM   500
#define IN_DIM  512
#define HID_DIM 2048
#define OUT_DIM 128
#define M_DIM   (B_DIM * T_DIM)          // 32000

// LIF constants
#define A_S1 0.81873075307798182f
#define SC1  0.90634623461009088f
#define A_M1 0.90483741803595952f
#define BM1  0.09516258196404048f
#define TH1  0.5f
#define A_S2 0.90483741803595952f
#define SC2  0.95162581964040482f
#define A_M2 0.95122942450071402f
#define BM2  0.04877057549928598f
#define TH2  1.0f

// ---------------- Scratch (device globals) ----------------
__device__ float    g_c1[(size_t)M_DIM * HID_DIM];   // 262 MB: X @ W1
__device__ float    g_c2[(size_t)M_DIM * OUT_DIM];   // 16.4 MB: spk1 @ W2
__device__ uint32_t g_bm[(size_t)M_DIM * 64];        // 8.2 MB spike bitmask

// ---------------- helpers ----------------
__device__ __forceinline__ uint32_t smem_u32(const void* p) {
    uint32_t a;
    asm("{ .reg .u64 t; cvta.to.shared.u64 t, %1; cvt.u32.u64 %0, t; }" : "=r"(a) : "l"(p));
    return a;
}
__device__ __forceinline__ void cp16(uint32_t d, const void* g) {
    asm volatile("cp.async.cg.shared.global [%0], [%1], 16;" :: "r"(d), "l"(g));
}
#define CP_COMMIT() asm volatile("cp.async.commit_group;" ::: "memory")
#define CP_WAIT0()  asm volatile("cp.async.wait_group 0;" ::: "memory")

// ---------------- SGEMM1: raster + 2-stage double buffer (bit-exact vs R1) -------
// C[M x N] = A[M x K] @ B[K x N]. BM=BN=128, BK=16, 256 threads.
// Thread (ty,tx): rows {4ty..+3, 64+4ty..+3} x cols {4tx..+3, 64+4tx..+3}.
// Per k: 2 LDS.128 A-broadcasts + 2 conflict-free LDS.128 B loads.
// B via cp.async (lands under previous tile's compute), A via LDG->reg->STS,
// prefetched 2 tiles ahead. ONE sync per tile. Ascending-k chain -> bit-exact.
#define GBM 128
#define GBN 128
#define GBK 16
#define APAD 132
#define NKT (IN_DIM / GBK)                // 32 K-tiles

__global__ __launch_bounds__(256, 2)
void sgemm1_kernel(const float* __restrict__ A, const float* __restrict__ B,
                   float* __restrict__ C) {
    __shared__ float As[2][GBK][APAD];
    __shared__ float Bs[2][GBK][GBN];

    const int tid  = threadIdx.x;
    const int ty   = tid >> 4;
    const int tx   = tid & 15;
    const int brow = blockIdx.y * GBM;
    const int bcol = blockIdx.x * GBN;

    const int arow = tid >> 2;            // A-load row (2 float4/thread)
    const int akc  = (tid & 3) << 2;
    const int brw  = tid >> 5;            // B-load row
    const int bc4  = (tid & 31) << 2;

    float4 areg[2];

    auto ldgA = [&](int c) {
        areg[0] = *reinterpret_cast<const float4*>(
            &A[(size_t)(brow + arow) * IN_DIM + c * GBK + akc]);
        areg[1] = *reinterpret_cast<const float4*>(
            &A[(size_t)(brow + 64 + arow) * IN_DIM + c * GBK + akc]);
    };
    auto stsA = [&](int st) {
        As[st][akc + 0][arow] = areg[0].x;
        As[st][akc + 1][arow] = areg[0].y;
        As[st][akc + 2][arow] = areg[0].z;
        As[st][akc + 3][arow] = areg[0].w;
        As[st][akc + 0][64 + arow] = areg[1].x;
        As[st][akc + 1][64 + arow] = areg[1].y;
        As[st][akc + 2][64 + arow] = areg[1].z;
        As[st][akc + 3][64 + arow] = areg[1].w;
    };
    auto cpB = [&](int c, int st) {
        cp16(smem_u32(&Bs[st][brw][bc4]),
             &B[(size_t)(c * GBK + brw) * HID_DIM + bcol + bc4]);
        cp16(smem_u32(&Bs[st][8 + brw][bc4]),
             &B[(size_t)(c * GBK + 8 + brw) * HID_DIM + bcol + bc4]);
    };

    float acc[8][8] = {};

    // prologue: stage 0 filled with tile 0; A tile 1 in regs
    ldgA(0);
    cpB(0, 0); CP_COMMIT();
    stsA(0);
    ldgA(1);

    for (int i = 0; i < NKT; i++) {
        const int st = i & 1;
        CP_WAIT0();                       // B_i landed
        __syncthreads();                  // tile-i smem visible; stage st^1 free
        if (i + 1 < NKT) {
            cpB(i + 1, st ^ 1); CP_COMMIT();
            stsA(st ^ 1);                 // areg holds tile i+1
        }
        if (i + 2 < NKT) ldgA(i + 2);     // prefetch under compute

        #pragma unroll
        for (int k = 0; k < GBK; k++) {
            float4 a0 = *reinterpret_cast<const float4*>(&As[st][k][4 * ty]);
            float4 a1 = *reinterpret_cast<const float4*>(&As[st][k][64 + 4 * ty]);
            float4 b0 = *reinterpret_cast<const float4*>(&Bs[st][k][4 * tx]);
            float4 b1 = *reinterpret_cast<const float4*>(&Bs[st][k][64 + 4 * tx]);
            float ar[8] = {a0.x, a0.y, a0.z, a0.w, a1.x, a1.y, a1.z, a1.w};
            float br[8] = {b0.x, b0.y, b0.z, b0.w, b1.x, b1.y, b1.z, b1.w};
            #pragma unroll
            for (int u = 0; u < 8; u++)
                #pragma unroll
                for (int v = 0; v < 8; v++)
                    acc[u][v] = fmaf(ar[u], br[v], acc[u][v]);
        }
    }

    #pragma unroll
    for (int i = 0; i < 4; i++) {
        float* r0 = &C[(size_t)(brow + 4 * ty + i) * HID_DIM + bcol];
        float* r1 = &C[(size_t)(brow + 64 + 4 * ty + i) * HID_DIM + bcol];
        *reinterpret_cast<float4*>(r0 + 4 * tx) =
            make_float4(acc[i][0], acc[i][1], acc[i][2], acc[i][3]);
        *reinterpret_cast<float4*>(r0 + 64 + 4 * tx) =
            make_float4(acc[i][4], acc[i][5], acc[i][6], acc[i][7]);
        *reinterpret_cast<float4*>(r1 + 4 * tx) =
            make_float4(acc[4 + i][0], acc[4 + i][1], acc[4 + i][2], acc[4 + i][3]);
        *reinterpret_cast<float4*>(r1 + 64 + 4 * tx) =
            make_float4(acc[4 + i][4], acc[4 + i][5], acc[4 + i][6], acc[4 + i][7]);
    }
}

// ---------------- Layer-1 LIF scan (+ spike bitmask via ballot) ----------------
__global__ __launch_bounds__(256)
void scan1_kernel(const float* __restrict__ c1, float* __restrict__ spk1,
                  float* __restrict__ mems1, uint32_t* __restrict__ bm) {
    int idx = blockIdx.x * blockDim.x + threadIdx.x;
    if (idx >= B_DIM * HID_DIM) return;
    int b = idx >> 11;
    int h = idx & (HID_DIM - 1);
    int lane = threadIdx.x & 31;
    int hw = h >> 5;
    size_t base = (size_t)b * T_DIM * HID_DIM + h;
    float syn = 0.f, mem = 0.f;
    for (int t = 0; t < T_DIM; t++) {
        size_t o = base + (size_t)t * HID_DIM;
        syn = A_S1 * syn + SC1 * c1[o];
        mem = A_M1 * mem + BM1 * syn;
        float s = (mem - TH1 > 0.f) ? 1.f : 0.f;
        mem -= s * TH1;
        spk1[o]  = s;
        mems1[o] = mem;
        uint32_t w = __ballot_sync(0xffffffffu, s > 0.f);
        if (lane == 0) bm[((size_t)b * T_DIM + t) * 64 + hw] = w;
    }
}

// ---------------- Sparse-exact GEMM2 (bit-identical; from R10) ----------------
#define SGK 64
__global__ __launch_bounds__(256, 2)
void spmm2_kernel(const uint32_t* __restrict__ bm, const float* __restrict__ w2,
                  float* __restrict__ c2) {
    __shared__ float ws[SGK][OUT_DIM];

    const int tid  = threadIdx.x;
    const int wid  = tid >> 5;
    const int lane = tid & 31;
    const int rbase = blockIdx.x * 128 + wid * 16;

    float acc[16][4] = {};

    for (int kt = 0; kt < HID_DIM / SGK; kt++) {
        __syncthreads();
        #pragma unroll
        for (int i = 0; i < 8; i++) {
            int s  = tid + i * 256;
            int kk = s >> 5;
            int c4 = (s & 31) * 4;
            *reinterpret_cast<float4*>(&ws[kk][c4]) =
                *reinterpret_cast<const float4*>(
                    &w2[(size_t)(kt * SGK + kk) * OUT_DIM + c4]);
        }
        __syncthreads();

        #pragma unroll
        for (int r = 0; r < 16; r++) {
            size_t m = (size_t)(rbase + r);
            uint32_t w0 = bm[m * 64 + kt * 2];
            uint32_t w1 = bm[m * 64 + kt * 2 + 1];
            while (w0) {
                int k = __ffs(w0) - 1; w0 &= w0 - 1;
                acc[r][0] += ws[k][lane];
                acc[r][1] += ws[k][lane + 32];
                acc[r][2] += ws[k][lane + 64];
                acc[r][3] += ws[k][lane + 96];
            }
            while (w1) {
                int k = __ffs(w1) - 1; w1 &= w1 - 1;
                acc[r][0] += ws[32 + k][lane];
                acc[r][1] += ws[32 + k][lane + 32];
                acc[r][2] += ws[32 + k][lane + 64];
                acc[r][3] += ws[32 + k][lane + 96];
            }
        }
    }

    #pragma unroll
    for (int r = 0; r < 16; r++) {
        float* cp = &c2[(size_t)(rbase + r) * OUT_DIM];
        cp[lane]      = acc[r][0];
        cp[lane + 32] = acc[r][1];
        cp[lane + 64] = acc[r][2];
        cp[lane + 96] = acc[r][3];
    }
}

// ---------------- Layer-2 LIF scan + time reduction ----------------
__global__ __launch_bounds__(256)
void scan2_kernel(const float* __restrict__ c2, float* __restrict__ out,
                  float* __restrict__ spk2, float* __restrict__ mems2) {
    int idx = blockIdx.x * blockDim.x + threadIdx.x;
    if (idx >= B_DIM * OUT_DIM) return;
    int b = idx >> 7;
    int o = idx & (OUT_DIM - 1);
    size_t base = (size_t)b * T_DIM * OUT_DIM + o;
    float syn = 0.f, mem = 0.f, acc = 0.f;
    for (int t = 0; t < T_DIM; t++) {
        size_t off = base + (size_t)t * OUT_DIM;
        syn = A_S2 * syn + SC2 * c2[off];
        mem = A_M2 * mem + BM2 * syn;
        float s = (mem - TH2 > 0.f) ? 1.f : 0.f;
        mem -= s * TH2;
        spk2[off]  = s;
        mems2[off] = mem;
        if (t > 0) acc += mem;
    }
    out[(size_t)b * OUT_DIM + o] = acc / (float)T_DIM;
}

// ---------------- Launch ----------------
extern "C" void kernel_launch(void* const* d_in, const int* in_sizes, int n_in,
                              void* d_out, int out_size) {
    const float* x  = (const float*)d_in[0];   // [B, T, IN]
    const float* w1 = (const float*)d_in[1];   // [IN, HID]
    const float* w2 = (const float*)d_in[2];   // [HID, OUT]

    float* out   = (float*)d_out;
    float* spk1  = out  + (size_t)B_DIM * OUT_DIM;
    float* mems1 = spk1 + (size_t)B_DIM * T_DIM * HID_DIM;
    float* spk2  = mems1 + (size_t)B_DIM * T_DIM * HID_DIM;
    float* mems2 = spk2 + (size_t)B_DIM * T_DIM * OUT_DIM;

    float*    c1; cudaGetSymbolAddress((void**)&c1, g_c1);
    float*    c2; cudaGetSymbolAddress((void**)&c2, g_c2);
    uint32_t* bm; cudaGetSymbolAddress((void**)&bm, g_bm);

    // Stage 1: C1 = X @ W1 (double-buffered raster SGEMM, bit-exact)
    {
        dim3 grid(HID_DIM / GBN, M_DIM / GBM);   // 16 x 250
        sgemm1_kernel<<<grid, 256>>>(x, w1, c1);
    }
    // Stage 2: layer-1 scan -> spk1, mems1, bitmask
    scan1_kernel<<<(B_DIM * HID_DIM) / 256, 256>>>(c1, spk1, mems1, bm);
    // Stage 3: C2 = spk1 @ W2 via sparse-exact bitmask GEMM
    spmm2_kernel<<<M_DIM / 128, 256>>>(bm, w2, c2);
    // Stage 4: layer-2 scan + output reduction
    scan2_kernel<<<(B_DIM * OUT_DIM) / 256, 256>>>(c2, out, spk2, mems2);
}